// round 11
// baseline (speedup 1.0000x reference)
#include <cuda_runtime.h>
#include <math.h>

#define D 128
#define T 64
#define BATCH 512
#define EPS 1e-5f
#define FULLMASK 0xffffffffu

#define SV_STRIDE 129   // conflict-free rows AND columns (129 mod 32 = 1)
#define TB (T * BATCH)

// -------- main recurrence: 1 warp per batch column, thread owns 4 dims --------
// Writes the output directly in (D,T,B) layout (scattered stores, L2-merged
// across adjacent-col warps); h_last slice appended at out + D*TB.
__global__ void __launch_bounds__(128) rnn_main_kernel(const float* __restrict__ inp,
                                                       const float* __restrict__ tgt_g,
                                                       const float* __restrict__ ret,
                                                       const float* __restrict__ W,
                                                       const float* __restrict__ b_g,
                                                       float* __restrict__ out) {
    extern __shared__ float smem[];
    float* sv = smem;                  // v padded: [128][129]
    float* xb = smem + D * SV_STRIDE;  // per-warp x buffer: [4][128] (16B aligned)

    int tid = threadIdx.x, lane = tid & 31, warp = tid >> 5;
    int col = blockIdx.x * 4 + warp;  // grid=128 -> col in [0,512)

    // ---- fused prep: thread tid row-normalizes row tid of W into smem.
    // Identical arithmetic to the reference: sum in j-order, sqrt, per-element div.
    {
        const float* wr = W + (size_t)tid * D;
        float ss = 0.f;
#pragma unroll 8
        for (int j = 0; j < D; j++) ss += wr[j] * wr[j];
        float nrm = fmaxf(sqrtf(ss), 1e-12f);
        for (int j = 0; j < D; j++) sv[tid * SV_STRIDE + j] = wr[j] / nrm;
    }

    // h0 / params load overlapped with v setup (no dependence on sv yet)
    float h4[4], tgt4[4], ab4[4], bp4[4], bn4[4];
#pragma unroll
    for (int q = 0; q < 4; q++) {
        int d = lane + 32 * q;
        tgt4[q] = tgt_g[d];
        ab4[q] = fabsf(b_g[d]);
        bp4[q] = ab4[q] + EPS;
        bn4[q] = -ab4[q] - EPS;
        float h0 = inp[(size_t)d * TB + col];  // input[:,0,:]
        h4[q] = h0;
        out[(size_t)d * TB + col] = h0;        // output[:,0,:]
    }

    // prefetch r for step t=1 (returns[:,0,:])
    float rp4[4];
#pragma unroll
    for (int q = 0; q < 4; q++)
        rp4[q] = ret[(size_t)(lane + 32 * q) * TB + col];

    __syncthreads();

    float rvd4[4];
#pragma unroll
    for (int q = 0; q < 4; q++) {
        int d = lane + 32 * q;
        rvd4[q] = 1.0f / sv[d * SV_STRIDE + d];
    }

    float* xw = xb + warp * D;

    for (int t = 1; t < T; t++) {
        // ---- adj = h*(1+r) / (1 + sum(h*r)) ----
        float r4[4], adj4[4], x4[4];
        float acc = 0.f;
#pragma unroll
        for (int q = 0; q < 4; q++) {
            r4[q] = rp4[q];
            acc += h4[q] * r4[q];
        }
#pragma unroll
        for (int o = 16; o; o >>= 1) acc += __shfl_xor_sync(FULLMASK, acc, o);
        float inv = 1.0f / (1.0f + acc);
#pragma unroll
        for (int q = 0; q < 4; q++) {
            adj4[q] = h4[q] * (1.0f + r4[q]) * inv;
            x4[q] = adj4[q] - tgt4[q];
            xw[lane + 32 * q] = x4[q];
        }
        __syncwarp();

        // prefetch next step's r (returns[:,t,:]) while the matvec runs
        if (t < T - 1) {
#pragma unroll
            for (int q = 0; q < 4; q++)
                rp4[q] = ret[(size_t)(lane + 32 * q) * TB + (size_t)t * BATCH + col];
        }

        // ---- s = v @ (adj - pi_bar): scalar row loads (stride 129, proven),
        // float4 broadcast of x (32 LDS.128 instead of 128 scalar LDS).
        float s4[4] = {0.f, 0.f, 0.f, 0.f};
        const float4* xw4 = (const float4*)xw;
#pragma unroll 4
        for (int i4 = 0; i4 < D / 4; i4++) {
            float4 x = xw4[i4];
            int i = 4 * i4;
#pragma unroll
            for (int q = 0; q < 4; q++) {
                const float* row = sv + (size_t)(lane + 32 * q) * SV_STRIDE + i;
                float a = fmaf(row[0], x.x, s4[q]);
                a = fmaf(row[1], x.y, a);
                a = fmaf(row[2], x.z, a);
                s4[q] = fmaf(row[3], x.w, a);
            }
        }
        __syncwarp();  // xw reads done before next-iteration writes

        // ---- delta + feas0 ----
        float del4[4];
        bool loc = true;
#pragma unroll
        for (int q = 0; q < 4; q++) {
            float s = s4[q];
            float num = 0.f;
            if (s > ab4[q]) num = ab4[q] - s;
            else if (s < -ab4[q]) num = -ab4[q] - s;
            del4[q] = num * rvd4[q];
            loc = loc && (s < bp4[q]) && (s > bn4[q]);
        }
        bool feas0 = __all_sync(FULLMASK, loc);
        bool judge = feas0;

        // ---- judge: any single-coordinate fix feasible? ----
        if (!judge) {
            unsigned mm[4];
            int ncand = 0;
#pragma unroll
            for (int sl = 0; sl < 4; sl++) {
                mm[sl] = __ballot_sync(FULLMASK, del4[sl] != 0.f);
                ncand += __popc(mm[sl]);
            }

            if (ncand > 3) {
                // ---- exact screen against one maximally-violated coordinate k*.
                float mv = 0.f;
#pragma unroll
                for (int q = 0; q < 4; q++)
                    mv = fmaxf(mv, fabsf(s4[q]) - ab4[q]);
                float wv = mv;
#pragma unroll
                for (int o = 16; o; o >>= 1)
                    wv = fmaxf(wv, __shfl_xor_sync(FULLMASK, wv, o));
                int myq = -1;
#pragma unroll
                for (int q = 0; q < 4; q++)
                    if (fabsf(s4[q]) - ab4[q] == wv) myq = q;
                unsigned own = __ballot_sync(FULLMASK, myq >= 0);
                int ln = __ffs(own) - 1;
                int qs = __shfl_sync(FULLMASK, myq, ln);  // uniform slot of k*
                float sA = (qs == 0) ? s4[0] : (qs == 1) ? s4[1] : (qs == 2) ? s4[2] : s4[3];
                float pA = (qs == 0) ? bp4[0] : (qs == 1) ? bp4[1] : (qs == 2) ? bp4[2] : bp4[3];
                float nA = (qs == 0) ? bn4[0] : (qs == 1) ? bn4[1] : (qs == 2) ? bn4[2] : bn4[3];
                float sstar = __shfl_sync(FULLMASK, sA, ln);
                float bpst = __shfl_sync(FULLMASK, pA, ln);
                float bnst = __shfl_sync(FULLMASK, nA, ln);
                int kstar = qs * 32 + ln;
                const float* rowk = sv + (size_t)kstar * SV_STRIDE;
#pragma unroll
                for (int sl = 0; sl < 4; sl++) {
                    float sn = fmaf(rowk[lane + 32 * sl], del4[sl], sstar);
                    bool okc = (del4[sl] != 0.f) && (sn < bpst) && (sn > bnst);
                    mm[sl] = __ballot_sync(FULLMASK, okc);
                }
            }

            // serial full test over (screened) survivors — unchanged semantics
#pragma unroll
            for (int sl = 0; sl < 4; sl++) {
                if (judge) continue;
                unsigned mask = mm[sl];
                while (mask) {
                    int ln = __ffs(mask) - 1;
                    mask &= mask - 1;
                    float di = __shfl_sync(FULLMASK, del4[sl], ln);
                    int i = sl * 32 + ln;
                    bool ok = true;
#pragma unroll
                    for (int q = 0; q < 4; q++) {
                        float sn = fmaf(sv[(lane + 32 * q) * SV_STRIDE + i], di, s4[q]);
                        ok = ok && (sn < bp4[q]) && (sn > bn4[q]);
                    }
                    if (__all_sync(FULLMASK, ok)) { judge = true; break; }
                }
            }
        }

        float hres4[4];
        if (judge) {
            if (feas0) {
#pragma unroll
                for (int q = 0; q < 4; q++) hres4[q] = adj4[q];
            } else {
                // ---- Gauss-Seidel sweep: ballot-driven, exact vs reference's
                // strictly-increasing single pass.
                float ssl[4], ht4[4];
#pragma unroll
                for (int q = 0; q < 4; q++) { ssl[q] = s4[q]; ht4[q] = adj4[q]; }
#pragma unroll
                for (int sl = 0; sl < 4; sl++) {
                    unsigned eligible = FULLMASK;
                    while (true) {
                        float s = ssl[sl];
                        float num = 0.f;
                        if (s > ab4[sl]) num = ab4[sl] - s;
                        else if (s < -ab4[sl]) num = -ab4[sl] - s;
                        unsigned mask = __ballot_sync(FULLMASK, num != 0.f) & eligible;
                        if (!mask) break;
                        int ln = __ffs(mask) - 1;
                        float cand = num * rvd4[sl];
                        float dj = __shfl_sync(FULLMASK, cand, ln);
                        int j = sl * 32 + ln;
#pragma unroll
                        for (int q = 0; q < 4; q++)
                            ssl[q] = fmaf(sv[(lane + 32 * q) * SV_STRIDE + j], dj, ssl[q]);
                        if (lane == ln) ht4[sl] += dj;
                        eligible = (ln == 31) ? 0u : (FULLMASK << (ln + 1));
                    }
                }
#pragma unroll
                for (int q = 0; q < 4; q++) hres4[q] = ht4[q];
            }
        } else {
            // ---- bisection collapsed to scalar alpha on segment pi + a*(h-pi)
            float am = __int_as_float(0x7f800000);  // +inf
#pragma unroll
            for (int q = 0; q < 4; q++) {
                float as = fabsf(s4[q]);
                float lim = (as > 0.f) ? bp4[q] / as : __int_as_float(0x7f800000);
                am = fminf(am, lim);
            }
#pragma unroll
            for (int o = 16; o; o >>= 1)
                am = fminf(am, __shfl_xor_sync(FULLMASK, am, o));
            float ain = 0.f, aout = 1.f, amid = 0.5f;
#pragma unroll
            for (int it = 0; it < 10; it++) {
                amid = ain + (aout - ain) * 0.5f;
                if (amid <= am) ain = amid; else aout = amid;
            }
#pragma unroll
            for (int q = 0; q < 4; q++)
                hres4[q] = fmaf(amid, x4[q], tgt4[q]);
        }

        // ---- direct output stores (fire-and-forget; L2 merges adjacent cols)
#pragma unroll
        for (int q = 0; q < 4; q++) {
            h4[q] = hres4[q];
            int d = lane + 32 * q;
            out[(size_t)d * TB + (size_t)t * BATCH + col] = hres4[q];
        }
        if (t == T - 1) {
#pragma unroll
            for (int q = 0; q < 4; q++) {
                int d = lane + 32 * q;
                out[(size_t)D * TB + (size_t)d * BATCH + col] = hres4[q];  // h_last
            }
        }
    }
}

extern "C" void kernel_launch(void* const* d_in, const int* in_sizes, int n_in,
                              void* d_out, int out_size) {
    const float* inp = (const float*)d_in[0];   // (D,T,B)
    const float* tgt = (const float*)d_in[1];   // (D,)
    const float* ret = (const float*)d_in[2];   // (D,T,B)
    // d_in[3] = hidden (unused by reference)
    const float* W = (const float*)d_in[4];     // (D,D)
    const float* bb = (const float*)d_in[5];    // (D,)
    float* out = (float*)d_out;                 // D*T*B output + D*B h_last

    size_t smem_bytes = (size_t)(D * SV_STRIDE + 4 * D) * sizeof(float);
    cudaFuncSetAttribute(rnn_main_kernel,
                         cudaFuncAttributeMaxDynamicSharedMemorySize,
                         (int)smem_bytes);
    rnn_main_kernel<<<128, 128, smem_bytes>>>(inp, tgt, ret, W, bb, out);
}

// round 13
// speedup vs baseline: 1.0043x; 1.0043x over previous
#include <cuda_runtime.h>
#include <math.h>

#define D 128
#define T 64
#define BATCH 512
#define EPS 1e-5f
#define FULLMASK 0xffffffffu

#define SV_STRIDE 129   // conflict-free rows AND columns (129 mod 32 = 1)
#define TB (T * BATCH)

// -------- scratch (device globals; no allocation allowed) --------
__device__ float g_outT[T * BATCH * D];      // output transposed: [t][b][d]

// -------- transpose outT [t][b][d] -> out (D,T,B); also emit h_last --------
__global__ void transpose_out_kernel(float* __restrict__ out) {
    __shared__ float tile[32][33];
    int t = blockIdx.z;
    int b0 = blockIdx.x * 32, d0 = blockIdx.y * 32;
    int tx = threadIdx.x, ty = threadIdx.y;
    const float* src = g_outT + (size_t)t * BATCH * D;
#pragma unroll
    for (int i = 0; i < 32; i += 8)
        tile[ty + i][tx] = src[(size_t)(b0 + ty + i) * D + (d0 + tx)];
    __syncthreads();
#pragma unroll
    for (int i = 0; i < 32; i += 8) {
        float val = tile[tx][ty + i];
        int d = d0 + ty + i;
        int b = b0 + tx;
        out[(size_t)d * TB + (size_t)t * BATCH + b] = val;
        if (t == T - 1)
            out[(size_t)D * TB + (size_t)d * BATCH + b] = val;
    }
}

// -------- main recurrence: 1 warp per batch column, thread owns 4 dims.
// Matvec is block-cooperative: v is read ONCE per block per step (4x less
// smem-crossbar traffic than per-warp redundant reads; L1tex was the wall).
__global__ void __launch_bounds__(128) rnn_main_kernel(const float* __restrict__ inp,
                                                       const float* __restrict__ tgt_g,
                                                       const float* __restrict__ ret,
                                                       const float* __restrict__ W,
                                                       const float* __restrict__ b_g) {
    extern __shared__ float smem[];
    float* sv = smem;                        // v padded: [128][129]
    float* xs = smem + D * SV_STRIDE;        // x transposed: [128][4] (16B aligned)
    float* sblk = xs + D * 4;                // s results: [4][128]

    int tid = threadIdx.x, lane = tid & 31, warp = tid >> 5;
    int col = blockIdx.x * 4 + warp;  // grid=128 -> col in [0,512)

    // ---- fused prep: thread tid row-normalizes row tid of W into smem.
    // Identical arithmetic to the reference: sum in j-order, sqrt, per-element div.
    {
        const float* wr = W + (size_t)tid * D;
        float ss = 0.f;
#pragma unroll 8
        for (int j = 0; j < D; j++) ss += wr[j] * wr[j];
        float nrm = fmaxf(sqrtf(ss), 1e-12f);
        for (int j = 0; j < D; j++) sv[tid * SV_STRIDE + j] = wr[j] / nrm;
    }

    // h0 / params load overlapped with v setup (no dependence on sv yet)
    float h4[4], tgt4[4], ab4[4], bp4[4], bn4[4];
#pragma unroll
    for (int q = 0; q < 4; q++) {
        int d = lane + 32 * q;
        tgt4[q] = tgt_g[d];
        ab4[q] = fabsf(b_g[d]);
        bp4[q] = ab4[q] + EPS;
        bn4[q] = -ab4[q] - EPS;
        float h0 = inp[(size_t)d * TB + col];  // input[:,0,:]
        h4[q] = h0;
        g_outT[(size_t)col * D + d] = h0;      // t = 0 slice
    }

    // prefetch r for step t=1 (returns[:,0,:])
    float rp4[4];
#pragma unroll
    for (int q = 0; q < 4; q++)
        rp4[q] = ret[(size_t)(lane + 32 * q) * TB + col];

    __syncthreads();

    float rvd4[4];
#pragma unroll
    for (int q = 0; q < 4; q++) {
        int d = lane + 32 * q;
        rvd4[q] = 1.0f / sv[d * SV_STRIDE + d];
    }

    for (int t = 1; t < T; t++) {
        // ---- adj = h*(1+r) / (1 + sum(h*r)) ----
        float r4[4], adj4[4], x4[4];
        float acc = 0.f;
#pragma unroll
        for (int q = 0; q < 4; q++) {
            r4[q] = rp4[q];
            acc += h4[q] * r4[q];
        }
#pragma unroll
        for (int o = 16; o; o >>= 1) acc += __shfl_xor_sync(FULLMASK, acc, o);
        float inv = 1.0f / (1.0f + acc);
#pragma unroll
        for (int q = 0; q < 4; q++) {
            adj4[q] = h4[q] * (1.0f + r4[q]) * inv;
            x4[q] = adj4[q] - tgt4[q];
            xs[(lane + 32 * q) * 4 + warp] = x4[q];  // transposed stage
        }

        // prefetch next step's r (returns[:,t,:]) — latency hidden by barrier+matvec
        if (t < T - 1) {
#pragma unroll
            for (int q = 0; q < 4; q++)
                rp4[q] = ret[(size_t)(lane + 32 * q) * TB + (size_t)t * BATCH + col];
        }

        __syncthreads();  // xs ready for all 4 columns

        // ---- cooperative matvec: thread tid = row, computes s_row for 4 cols.
        // v read once per block; x via one broadcast LDS.128 per i.
        // Summation order over i identical to reference accumulate -> bit-identical s.
        {
            float sc0 = 0.f, sc1 = 0.f, sc2 = 0.f, sc3 = 0.f;
            const float* vrow = sv + (size_t)tid * SV_STRIDE;
            const float4* xs4 = (const float4*)xs;
#pragma unroll 4
            for (int i = 0; i < D; i++) {
                float vv = vrow[i];
                float4 xx = xs4[i];
                sc0 = fmaf(vv, xx.x, sc0);
                sc1 = fmaf(vv, xx.y, sc1);
                sc2 = fmaf(vv, xx.z, sc2);
                sc3 = fmaf(vv, xx.w, sc3);
            }
            sblk[0 * D + tid] = sc0;
            sblk[1 * D + tid] = sc1;
            sblk[2 * D + tid] = sc2;
            sblk[3 * D + tid] = sc3;
        }
        __syncthreads();  // s ready

        float s4[4];
#pragma unroll
        for (int q = 0; q < 4; q++)
            s4[q] = sblk[warp * D + lane + 32 * q];

        // ---- delta + feas0 ----
        float del4[4];
        bool loc = true;
#pragma unroll
        for (int q = 0; q < 4; q++) {
            float s = s4[q];
            float num = 0.f;
            if (s > ab4[q]) num = ab4[q] - s;
            else if (s < -ab4[q]) num = -ab4[q] - s;
            del4[q] = num * rvd4[q];
            loc = loc && (s < bp4[q]) && (s > bn4[q]);
        }
        bool feas0 = __all_sync(FULLMASK, loc);
        bool judge = feas0;

        // ---- judge: any single-coordinate fix feasible? ----
        if (!judge) {
            unsigned mm[4];
            int ncand = 0;
#pragma unroll
            for (int sl = 0; sl < 4; sl++) {
                mm[sl] = __ballot_sync(FULLMASK, del4[sl] != 0.f);
                ncand += __popc(mm[sl]);
            }

            if (ncand > 3) {
                // ---- exact screen against one maximally-violated coordinate k*.
                float mv = 0.f;
#pragma unroll
                for (int q = 0; q < 4; q++)
                    mv = fmaxf(mv, fabsf(s4[q]) - ab4[q]);
                float wv = mv;
#pragma unroll
                for (int o = 16; o; o >>= 1)
                    wv = fmaxf(wv, __shfl_xor_sync(FULLMASK, wv, o));
                int myq = -1;
#pragma unroll
                for (int q = 0; q < 4; q++)
                    if (fabsf(s4[q]) - ab4[q] == wv) myq = q;
                unsigned own = __ballot_sync(FULLMASK, myq >= 0);
                int ln = __ffs(own) - 1;
                int qs = __shfl_sync(FULLMASK, myq, ln);  // uniform slot of k*
                float sA = (qs == 0) ? s4[0] : (qs == 1) ? s4[1] : (qs == 2) ? s4[2] : s4[3];
                float pA = (qs == 0) ? bp4[0] : (qs == 1) ? bp4[1] : (qs == 2) ? bp4[2] : bp4[3];
                float nA = (qs == 0) ? bn4[0] : (qs == 1) ? bn4[1] : (qs == 2) ? bn4[2] : bn4[3];
                float sstar = __shfl_sync(FULLMASK, sA, ln);
                float bpst = __shfl_sync(FULLMASK, pA, ln);
                float bnst = __shfl_sync(FULLMASK, nA, ln);
                int kstar = qs * 32 + ln;
                const float* rowk = sv + (size_t)kstar * SV_STRIDE;
#pragma unroll
                for (int sl = 0; sl < 4; sl++) {
                    float sn = fmaf(rowk[lane + 32 * sl], del4[sl], sstar);
                    bool okc = (del4[sl] != 0.f) && (sn < bpst) && (sn > bnst);
                    mm[sl] = __ballot_sync(FULLMASK, okc);
                }
            }

            // serial full test over (screened) survivors — unchanged semantics
#pragma unroll
            for (int sl = 0; sl < 4; sl++) {
                if (judge) continue;
                unsigned mask = mm[sl];
                while (mask) {
                    int ln = __ffs(mask) - 1;
                    mask &= mask - 1;
                    float di = __shfl_sync(FULLMASK, del4[sl], ln);
                    int i = sl * 32 + ln;
                    bool ok = true;
#pragma unroll
                    for (int q = 0; q < 4; q++) {
                        float sn = fmaf(sv[(lane + 32 * q) * SV_STRIDE + i], di, s4[q]);
                        ok = ok && (sn < bp4[q]) && (sn > bn4[q]);
                    }
                    if (__all_sync(FULLMASK, ok)) { judge = true; break; }
                }
            }
        }

        float hres4[4];
        if (judge) {
            if (feas0) {
#pragma unroll
                for (int q = 0; q < 4; q++) hres4[q] = adj4[q];
            } else {
                // ---- Gauss-Seidel sweep: ballot-driven, exact vs reference's
                // strictly-increasing single pass.
                float ssl[4], ht4[4];
#pragma unroll
                for (int q = 0; q < 4; q++) { ssl[q] = s4[q]; ht4[q] = adj4[q]; }
#pragma unroll
                for (int sl = 0; sl < 4; sl++) {
                    unsigned eligible = FULLMASK;
                    while (true) {
                        float s = ssl[sl];
                        float num = 0.f;
                        if (s > ab4[sl]) num = ab4[sl] - s;
                        else if (s < -ab4[sl]) num = -ab4[sl] - s;
                        unsigned mask = __ballot_sync(FULLMASK, num != 0.f) & eligible;
                        if (!mask) break;
                        int ln = __ffs(mask) - 1;
                        float cand = num * rvd4[sl];
                        float dj = __shfl_sync(FULLMASK, cand, ln);
                        int j = sl * 32 + ln;
#pragma unroll
                        for (int q = 0; q < 4; q++)
                            ssl[q] = fmaf(sv[(lane + 32 * q) * SV_STRIDE + j], dj, ssl[q]);
                        if (lane == ln) ht4[sl] += dj;
                        eligible = (ln == 31) ? 0u : (FULLMASK << (ln + 1));
                    }
                }
#pragma unroll
                for (int q = 0; q < 4; q++) hres4[q] = ht4[q];
            }
        } else {
            // ---- bisection collapsed to scalar alpha on segment pi + a*(h-pi)
            float am = __int_as_float(0x7f800000);  // +inf
#pragma unroll
            for (int q = 0; q < 4; q++) {
                float as = fabsf(s4[q]);
                float lim = (as > 0.f) ? bp4[q] / as : __int_as_float(0x7f800000);
                am = fminf(am, lim);
            }
#pragma unroll
            for (int o = 16; o; o >>= 1)
                am = fminf(am, __shfl_xor_sync(FULLMASK, am, o));
            float ain = 0.f, aout = 1.f, amid = 0.5f;
#pragma unroll
            for (int it = 0; it < 10; it++) {
                amid = ain + (aout - ain) * 0.5f;
                if (amid <= am) ain = amid; else aout = amid;
            }
#pragma unroll
            for (int q = 0; q < 4; q++)
                hres4[q] = fmaf(amid, x4[q], tgt4[q]);
        }

#pragma unroll
        for (int q = 0; q < 4; q++) {
            h4[q] = hres4[q];
            g_outT[((size_t)t * BATCH + col) * D + (lane + 32 * q)] = hres4[q];
        }
    }
}

extern "C" void kernel_launch(void* const* d_in, const int* in_sizes, int n_in,
                              void* d_out, int out_size) {
    const float* inp = (const float*)d_in[0];   // (D,T,B)
    const float* tgt = (const float*)d_in[1];   // (D,)
    const float* ret = (const float*)d_in[2];   // (D,T,B)
    // d_in[3] = hidden (unused by reference)
    const float* W = (const float*)d_in[4];     // (D,D)
    const float* bb = (const float*)d_in[5];    // (D,)
    float* out = (float*)d_out;                 // D*T*B output + D*B h_last

    size_t smem_bytes = (size_t)(D * SV_STRIDE + D * 4 + 4 * D) * sizeof(float);
    cudaFuncSetAttribute(rnn_main_kernel,
                         cudaFuncAttributeMaxDynamicSharedMemorySize,
                         (int)smem_bytes);
    rnn_main_kernel<<<128, 128, smem_bytes>>>(inp, tgt, ret, W, bb);

    dim3 tb(32, 8);
    transpose_out_kernel<<<dim3(BATCH / 32, D / 32, T), tb>>>(out);
}

// round 14
// speedup vs baseline: 1.1140x; 1.1092x over previous
#include <cuda_runtime.h>
#include <math.h>

#define D 128
#define T 64
#define BATCH 512
#define EPS 1e-5f
#define FULLMASK 0xffffffffu

#define SV_STRIDE 129   // conflict-free rows AND columns (129 mod 32 = 1)
#define TB (T * BATCH)

// -------- scratch (device globals; no allocation allowed) --------
__device__ float g_outT[T * BATCH * D];      // output transposed: [t][b][d]

// -------- transpose outT [t][b][d] -> out (D,T,B); also emit h_last --------
__global__ void transpose_out_kernel(float* __restrict__ out) {
    __shared__ float tile[32][33];
    int t = blockIdx.z;
    int b0 = blockIdx.x * 32, d0 = blockIdx.y * 32;
    int tx = threadIdx.x, ty = threadIdx.y;
    const float* src = g_outT + (size_t)t * BATCH * D;
#pragma unroll
    for (int i = 0; i < 32; i += 8)
        tile[ty + i][tx] = src[(size_t)(b0 + ty + i) * D + (d0 + tx)];
    __syncthreads();
#pragma unroll
    for (int i = 0; i < 32; i += 8) {
        float val = tile[tx][ty + i];
        int d = d0 + ty + i;
        int b = b0 + tx;
        out[(size_t)d * TB + (size_t)t * BATCH + b] = val;
        if (t == T - 1)
            out[(size_t)D * TB + (size_t)d * BATCH + b] = val;
    }
}

// -------- main recurrence: 1 warp per batch column, thread owns 4 dims.
// Warps stay independent (no block barriers in the hot loop). Matvec uses
// packed row-pair loads (pv01/pv23) and the shfl-reduction is interleaved
// between matvec chunks so the in-order warp never stalls on it.
__global__ void __launch_bounds__(128) rnn_main_kernel(const float* __restrict__ inp,
                                                       const float* __restrict__ tgt_g,
                                                       const float* __restrict__ ret,
                                                       const float* __restrict__ W,
                                                       const float* __restrict__ b_g) {
    extern __shared__ float smem[];
    float* sv = smem;                          // v padded: [128][129]
    float* pv01 = smem + D * SV_STRIDE;        // float2 pairs rows (l, l+32): [128][32]
    float* pv23 = pv01 + D * 32 * 2;           // float2 pairs rows (l+64, l+96)
    float* xb = pv23 + D * 32 * 2;             // per-warp x/u buffer: [4][128]

    int tid = threadIdx.x, lane = tid & 31, warp = tid >> 5;
    int col = blockIdx.x * 4 + warp;  // grid=128 -> col in [0,512)

    // ---- fused prep: thread tid row-normalizes row tid of W into smem.
    {
        const float* wr = W + (size_t)tid * D;
        float ss = 0.f;
#pragma unroll 8
        for (int j = 0; j < D; j++) ss += wr[j] * wr[j];
        float nrm = fmaxf(sqrtf(ss), 1e-12f);
        for (int j = 0; j < D; j++) sv[tid * SV_STRIDE + j] = wr[j] / nrm;
    }

    // h0 / params load overlapped with v setup
    float h4[4], tgt4[4], ab4[4], bp4[4], bn4[4];
#pragma unroll
    for (int q = 0; q < 4; q++) {
        int d = lane + 32 * q;
        tgt4[q] = tgt_g[d];
        ab4[q] = fabsf(b_g[d]);
        bp4[q] = ab4[q] + EPS;
        bn4[q] = -ab4[q] - EPS;
        float h0 = inp[(size_t)d * TB + col];  // input[:,0,:]
        h4[q] = h0;
        g_outT[(size_t)col * D + d] = h0;      // t = 0 slice
    }

    // prefetch r for step t=1 (returns[:,0,:])
    float rp4[4];
#pragma unroll
    for (int q = 0; q < 4; q++)
        rp4[q] = ret[(size_t)(lane + 32 * q) * TB + col];

    __syncthreads();  // sv complete

    // ---- build packed row-pair copies for the matvec
    for (int idx = tid; idx < D * 32; idx += 128) {
        int i = idx >> 5, l = idx & 31;
        ((float2*)pv01)[idx] = make_float2(sv[l * SV_STRIDE + i],
                                           sv[(l + 32) * SV_STRIDE + i]);
        ((float2*)pv23)[idx] = make_float2(sv[(l + 64) * SV_STRIDE + i],
                                           sv[(l + 96) * SV_STRIDE + i]);
    }

    float rvd4[4];
#pragma unroll
    for (int q = 0; q < 4; q++) {
        int d = lane + 32 * q;
        rvd4[q] = 1.0f / sv[d * SV_STRIDE + d];
    }

    __syncthreads();  // pv ready

    float* xw = xb + warp * D;
    const float4* xw4 = (const float4*)xw;
    const float2* p01 = (const float2*)pv01;
    const float2* p23 = (const float2*)pv23;

    // packed matvec chunk: 4 x-quads (16 columns) starting at i4=base
    float vu0, vu1, vu2, vu3;
    auto mv_chunk = [&](int base) {
#pragma unroll
        for (int i4 = base; i4 < base + 4; i4++) {
            float4 x = xw4[i4];
            int i = 4 * i4;
#pragma unroll
            for (int u = 0; u < 4; u++) {
                float xi = (u == 0) ? x.x : (u == 1) ? x.y : (u == 2) ? x.z : x.w;
                float2 a = p01[(i + u) * 32 + lane];
                float2 b = p23[(i + u) * 32 + lane];
                vu0 = fmaf(a.x, xi, vu0);
                vu1 = fmaf(a.y, xi, vu1);
                vu2 = fmaf(b.x, xi, vu2);
                vu3 = fmaf(b.y, xi, vu3);
            }
        }
    };

    // ---- one-time vt = v @ tgt (same code path as the step matvec)
    float vt4[4];
    {
#pragma unroll
        for (int q = 0; q < 4; q++) xw[lane + 32 * q] = tgt4[q];
        __syncwarp();
        vu0 = vu1 = vu2 = vu3 = 0.f;
        for (int c = 0; c < 32; c += 4) mv_chunk(c);
        vt4[0] = vu0; vt4[1] = vu1; vt4[2] = vu2; vt4[3] = vu3;
        __syncwarp();
    }

    for (int t = 1; t < T; t++) {
        // ---- u = h*(1+r); acc = sum(h*r) (reduction deferred into matvec) ----
        float r4[4], u4[4];
        float red = 0.f;
#pragma unroll
        for (int q = 0; q < 4; q++) {
            r4[q] = rp4[q];
            red += h4[q] * r4[q];
            u4[q] = h4[q] * (1.0f + r4[q]);
            xw[lane + 32 * q] = u4[q];
        }
        __syncwarp();

        // prefetch next step's r while the matvec runs
        if (t < T - 1) {
#pragma unroll
            for (int q = 0; q < 4; q++)
                rp4[q] = ret[(size_t)(lane + 32 * q) * TB + (size_t)t * BATCH + col];
        }

        // ---- matvec on u with the shfl reduction interleaved between chunks
        vu0 = vu1 = vu2 = vu3 = 0.f;
        mv_chunk(0);
        red += __shfl_xor_sync(FULLMASK, red, 16);
        mv_chunk(4);
        red += __shfl_xor_sync(FULLMASK, red, 8);
        mv_chunk(8);
        red += __shfl_xor_sync(FULLMASK, red, 4);
        mv_chunk(12);
        red += __shfl_xor_sync(FULLMASK, red, 2);
        mv_chunk(16);
        red += __shfl_xor_sync(FULLMASK, red, 1);
        mv_chunk(20);
        float inv = 1.0f / (1.0f + red);
        mv_chunk(24);
        mv_chunk(28);
        __syncwarp();  // xw reads done before next-iteration writes

        // s = inv*(v@u) - v@tgt ; adj = u*inv ; x = adj - tgt
        float s4[4], adj4[4], x4[4];
        s4[0] = fmaf(vu0, inv, -vt4[0]);
        s4[1] = fmaf(vu1, inv, -vt4[1]);
        s4[2] = fmaf(vu2, inv, -vt4[2]);
        s4[3] = fmaf(vu3, inv, -vt4[3]);
#pragma unroll
        for (int q = 0; q < 4; q++) {
            adj4[q] = u4[q] * inv;
            x4[q] = adj4[q] - tgt4[q];
        }

        // ---- delta + feas0 ----
        float del4[4];
        bool loc = true;
#pragma unroll
        for (int q = 0; q < 4; q++) {
            float s = s4[q];
            float num = 0.f;
            if (s > ab4[q]) num = ab4[q] - s;
            else if (s < -ab4[q]) num = -ab4[q] - s;
            del4[q] = num * rvd4[q];
            loc = loc && (s < bp4[q]) && (s > bn4[q]);
        }
        bool feas0 = __all_sync(FULLMASK, loc);
        bool judge = feas0;

        // ---- judge: any single-coordinate fix feasible? ----
        if (!judge) {
            unsigned mm[4];
            int ncand = 0;
#pragma unroll
            for (int sl = 0; sl < 4; sl++) {
                mm[sl] = __ballot_sync(FULLMASK, del4[sl] != 0.f);
                ncand += __popc(mm[sl]);
            }

            if (ncand > 3) {
                // ---- exact screen against one maximally-violated coordinate k*.
                float mv = 0.f;
#pragma unroll
                for (int q = 0; q < 4; q++)
                    mv = fmaxf(mv, fabsf(s4[q]) - ab4[q]);
                float wv = mv;
#pragma unroll
                for (int o = 16; o; o >>= 1)
                    wv = fmaxf(wv, __shfl_xor_sync(FULLMASK, wv, o));
                int myq = -1;
#pragma unroll
                for (int q = 0; q < 4; q++)
                    if (fabsf(s4[q]) - ab4[q] == wv) myq = q;
                unsigned own = __ballot_sync(FULLMASK, myq >= 0);
                int ln = __ffs(own) - 1;
                int qs = __shfl_sync(FULLMASK, myq, ln);  // uniform slot of k*
                float sA = (qs == 0) ? s4[0] : (qs == 1) ? s4[1] : (qs == 2) ? s4[2] : s4[3];
                float pA = (qs == 0) ? bp4[0] : (qs == 1) ? bp4[1] : (qs == 2) ? bp4[2] : bp4[3];
                float nA = (qs == 0) ? bn4[0] : (qs == 1) ? bn4[1] : (qs == 2) ? bn4[2] : bn4[3];
                float sstar = __shfl_sync(FULLMASK, sA, ln);
                float bpst = __shfl_sync(FULLMASK, pA, ln);
                float bnst = __shfl_sync(FULLMASK, nA, ln);
                int kstar = qs * 32 + ln;
                const float* rowk = sv + (size_t)kstar * SV_STRIDE;
#pragma unroll
                for (int sl = 0; sl < 4; sl++) {
                    float sn = fmaf(rowk[lane + 32 * sl], del4[sl], sstar);
                    bool okc = (del4[sl] != 0.f) && (sn < bpst) && (sn > bnst);
                    mm[sl] = __ballot_sync(FULLMASK, okc);
                }
            }

            // serial full test over (screened) survivors — unchanged semantics
#pragma unroll
            for (int sl = 0; sl < 4; sl++) {
                if (judge) continue;
                unsigned mask = mm[sl];
                while (mask) {
                    int ln = __ffs(mask) - 1;
                    mask &= mask - 1;
                    float di = __shfl_sync(FULLMASK, del4[sl], ln);
                    int i = sl * 32 + ln;
                    bool ok = true;
#pragma unroll
                    for (int q = 0; q < 4; q++) {
                        float sn = fmaf(sv[(lane + 32 * q) * SV_STRIDE + i], di, s4[q]);
                        ok = ok && (sn < bp4[q]) && (sn > bn4[q]);
                    }
                    if (__all_sync(FULLMASK, ok)) { judge = true; break; }
                }
            }
        }

        float hres4[4];
        if (judge) {
            if (feas0) {
#pragma unroll
                for (int q = 0; q < 4; q++) hres4[q] = adj4[q];
            } else {
                // ---- Gauss-Seidel sweep: ballot-driven, exact vs reference's
                // strictly-increasing single pass.
                float ssl[4], ht4[4];
#pragma unroll
                for (int q = 0; q < 4; q++) { ssl[q] = s4[q]; ht4[q] = adj4[q]; }
#pragma unroll
                for (int sl = 0; sl < 4; sl++) {
                    unsigned eligible = FULLMASK;
                    while (true) {
                        float s = ssl[sl];
                        float num = 0.f;
                        if (s > ab4[sl]) num = ab4[sl] - s;
                        else if (s < -ab4[sl]) num = -ab4[sl] - s;
                        unsigned mask = __ballot_sync(FULLMASK, num != 0.f) & eligible;
                        if (!mask) break;
                        int ln = __ffs(mask) - 1;
                        float cand = num * rvd4[sl];
                        float dj = __shfl_sync(FULLMASK, cand, ln);
                        int j = sl * 32 + ln;
#pragma unroll
                        for (int q = 0; q < 4; q++)
                            ssl[q] = fmaf(sv[(lane + 32 * q) * SV_STRIDE + j], dj, ssl[q]);
                        if (lane == ln) ht4[sl] += dj;
                        eligible = (ln == 31) ? 0u : (FULLMASK << (ln + 1));
                    }
                }
#pragma unroll
                for (int q = 0; q < 4; q++) hres4[q] = ht4[q];
            }
        } else {
            // ---- bisection collapsed to scalar alpha on segment pi + a*(h-pi)
            float am = __int_as_float(0x7f800000);  // +inf
#pragma unroll
            for (int q = 0; q < 4; q++) {
                float as = fabsf(s4[q]);
                float lim = (as > 0.f) ? bp4[q] / as : __int_as_float(0x7f800000);
                am = fminf(am, lim);
            }
#pragma unroll
            for (int o = 16; o; o >>= 1)
                am = fminf(am, __shfl_xor_sync(FULLMASK, am, o));
            float ain = 0.f, aout = 1.f, amid = 0.5f;
#pragma unroll
            for (int it = 0; it < 10; it++) {
                amid = ain + (aout - ain) * 0.5f;
                if (amid <= am) ain = amid; else aout = amid;
            }
#pragma unroll
            for (int q = 0; q < 4; q++)
                hres4[q] = fmaf(amid, x4[q], tgt4[q]);
        }

#pragma unroll
        for (int q = 0; q < 4; q++) {
            h4[q] = hres4[q];
            g_outT[((size_t)t * BATCH + col) * D + (lane + 32 * q)] = hres4[q];
        }
    }
}

extern "C" void kernel_launch(void* const* d_in, const int* in_sizes, int n_in,
                              void* d_out, int out_size) {
    const float* inp = (const float*)d_in[0];   // (D,T,B)
    const float* tgt = (const float*)d_in[1];   // (D,)
    const float* ret = (const float*)d_in[2];   // (D,T,B)
    // d_in[3] = hidden (unused by reference)
    const float* W = (const float*)d_in[4];     // (D,D)
    const float* bb = (const float*)d_in[5];    // (D,)
    float* out = (float*)d_out;                 // D*T*B output + D*B h_last

    size_t smem_bytes =
        (size_t)(D * SV_STRIDE + 2 * D * 32 * 2 + 4 * D) * sizeof(float);
    cudaFuncSetAttribute(rnn_main_kernel,
                         cudaFuncAttributeMaxDynamicSharedMemorySize,
                         (int)smem_bytes);
    rnn_main_kernel<<<128, 128, smem_bytes>>>(inp, tgt, ret, W, bb);

    dim3 tb(32, 8);
    transpose_out_kernel<<<dim3(BATCH / 32, D / 32, T), tb>>>(out);
}